// round 13
// baseline (speedup 1.0000x reference)
#include <cuda_runtime.h>
#include <cuda_fp16.h>
#include <cstdint>

// ---------------------------------------------------------------------------
// Problem shape constants
// ---------------------------------------------------------------------------
#define BATCH   8
#define SEQ     2048
#define DIM     512
#define NOUT    1026          // N_FFT + 2
#define NBINS   513           // N_FFT/2 + 1
#define NFFT    1024
#define HOP     256
#define PADQ    384           // (WIN_LEN - HOP)/2
#define MROWS   (BATCH*SEQ)   // 16384
#define OUTB    524288        // per-batch output length = SEQ*HOP
#define NPAD    1152          // padded N (9 * 128)

// GEMM tiling: CTA 128x128, 4 warps (128 thr), warp tile 64x64
#define BMg     128
#define BNg     128
#define BKg     32
#define NCHUNK  (DIM/BKg)     // 16
#define OFF_B   10240         // A stage: 128 rows x 80B
#define STAGEB  20480         // + B stage: 128 rows x 80B
#define DYNSM   (2*STAGEB)    // 40960

// ---------------------------------------------------------------------------
// Device scratch (allocation-free contract)
// ---------------------------------------------------------------------------
__device__ float          g_H[(size_t)MROWS * NOUT];    // h = xW + b
__device__ float          g_F[(size_t)MROWS * NFFT];    // windowed irfft frames
__device__ unsigned short g_Ax[(size_t)MROWS * DIM];    // fp16 x
__device__ unsigned short g_Wx[(size_t)NPAD * DIM];     // fp16 W^T [n][k]
__device__ float          g_win[NFFT];                  // hann window
__device__ float          g_win2[NFFT];                 // hann^2

// ---------------------------------------------------------------------------
// Portable PTX helpers
// ---------------------------------------------------------------------------
__device__ __forceinline__ uint32_t smem_u32(const void* p) {
    uint32_t a;
    asm("{ .reg .u64 t; cvta.to.shared.u64 t, %1; cvt.u32.u64 %0, t; }"
        : "=r"(a) : "l"(p));
    return a;
}
__device__ __forceinline__ void cp16(uint32_t dst, const void* src) {
    asm volatile("cp.async.cg.shared.global [%0], [%1], 16;"
                 :: "r"(dst), "l"(src) : "memory");
}
#define CP_COMMIT() asm volatile("cp.async.commit_group;" ::: "memory")
#define CP_WAIT0()  asm volatile("cp.async.wait_group 0;" ::: "memory")

__device__ __forceinline__ void mma16816(float* c, const uint32_t* a, const uint32_t* b) {
    asm volatile(
        "mma.sync.aligned.m16n8k16.row.col.f32.f16.f16.f32 "
        "{%0,%1,%2,%3}, {%4,%5,%6,%7}, {%8,%9}, {%0,%1,%2,%3};"
        : "+f"(c[0]), "+f"(c[1]), "+f"(c[2]), "+f"(c[3])
        : "r"(a[0]), "r"(a[1]), "r"(a[2]), "r"(a[3]), "r"(b[0]), "r"(b[1]));
}
__device__ __forceinline__ void ldsm_x4(uint32_t& r0, uint32_t& r1, uint32_t& r2,
                                        uint32_t& r3, uint32_t addr) {
    asm volatile("ldmatrix.sync.aligned.m8n8.x4.shared.b16 {%0,%1,%2,%3}, [%4];"
                 : "=r"(r0), "=r"(r1), "=r"(r2), "=r"(r3) : "r"(addr));
}

// ---------------------------------------------------------------------------
// Prep kernels: fp32 -> fp16
// ---------------------------------------------------------------------------
__global__ __launch_bounds__(256) void convert_x_kernel(const float* __restrict__ x)
{
    size_t v = (size_t)blockIdx.x * 256 + threadIdx.x;   // one float4 per thread
    float4 a = *reinterpret_cast<const float4*>(x + v * 4);
    __half2 p0 = __floats2half2_rn(a.x, a.y);
    __half2 p1 = __floats2half2_rn(a.z, a.w);
    uint2 pv;
    pv.x = *reinterpret_cast<uint32_t*>(&p0);
    pv.y = *reinterpret_cast<uint32_t*>(&p1);
    *reinterpret_cast<uint2*>(g_Ax + v * 4) = pv;
}

// Coalesced W transpose via 32x32 smem tile: read W[k][n], write Wt[n][k] fp16
__global__ __launch_bounds__(256) void convert_w_kernel(const float* __restrict__ W)
{
    __shared__ float tile[32][33];
    const int n0 = blockIdx.x * 32;      // 0..1151 (36 tiles)
    const int k0 = blockIdx.y * 32;      // 0..511  (16 tiles)
    const int tx = threadIdx.x & 31;
    const int ty = threadIdx.x >> 5;     // 0..7

#pragma unroll
    for (int i = 0; i < 32; i += 8) {
        int k = k0 + ty + i;
        int n = n0 + tx;
        tile[ty + i][tx] = (n < NOUT) ? W[(size_t)k * NOUT + n] : 0.0f;
    }
    __syncthreads();
#pragma unroll
    for (int i = 0; i < 32; i += 8) {
        int n = n0 + ty + i;
        int k = k0 + tx;
        __half hv = __float2half_rn(tile[tx][ty + i]);
        g_Wx[(size_t)n * DIM + k] = *reinterpret_cast<unsigned short*>(&hv);
    }
}

__global__ __launch_bounds__(256) void window_kernel()
{
    int n = blockIdx.x * 256 + threadIdx.x;   // 0..1023
    float w = 0.5f * (1.0f - cosf(6.283185307179586476e0f * (float)n / 1024.0f));
    g_win[n]  = w;
    g_win2[n] = w * w;
}

// ---------------------------------------------------------------------------
// fp16 mma.sync GEMM: CTA 128x128, 4 warps, warp tile 64x64,
// 2-stage cp.async, one __syncthreads per chunk.
// ---------------------------------------------------------------------------
__device__ __forceinline__ void load_stage(int s, int kc, int tid,
                                           int m0, int n0, uint32_t smb)
{
    const uint32_t sb = smb + s * STAGEB;
    const int kk = kc * BKg;
#pragma unroll
    for (int i = 0; i < 4; i++) {
        int id = tid + i * 128;            // 0..511
        int row = id >> 2, c = id & 3;     // 128 rows x 4 16B-chunks
        size_t goffA = (size_t)(m0 + row) * DIM + kk + c * 8;
        size_t goffB = (size_t)(n0 + row) * DIM + kk + c * 8;
        cp16(sb + row * 80 + c * 16,         g_Ax + goffA);
        cp16(sb + OFF_B + row * 80 + c * 16, g_Wx + goffB);
    }
}

__global__ __launch_bounds__(128) void gemm_mma_kernel(const float* __restrict__ bias)
{
    extern __shared__ char sm[];
    const int tid  = threadIdx.x;
    const int n0   = blockIdx.x * BNg;
    const int m0   = blockIdx.y * BMg;
    const int wid  = tid >> 5, lane = tid & 31;
    const int g    = lane >> 2, t = lane & 3;
    const int wM   = (wid & 1) * 64;
    const int wN   = (wid >> 1) * 64;
    const uint32_t smb = smem_u32(sm);

    const int mat = lane >> 3;
    const int mr  = lane & 7;
    const int aRow = ((mat & 1) << 3) + mr;
    const int aK   = (mat >> 1) << 3;
    const int bRow = ((mat >> 1) << 3) + mr;
    const int bK   = (mat & 1) << 3;

    float acc[4][8][4];
#pragma unroll
    for (int i = 0; i < 4; i++)
#pragma unroll
        for (int j = 0; j < 8; j++)
#pragma unroll
            for (int q = 0; q < 4; q++) acc[i][j][q] = 0.f;

    load_stage(0, 0, tid, m0, n0, smb);
    CP_COMMIT();

    for (int kc = 0; kc < NCHUNK; kc++) {
        CP_WAIT0();
        __syncthreads();

        if (kc + 1 < NCHUNK) {
            load_stage((kc + 1) & 1, kc + 1, tid, m0, n0, smb);
            CP_COMMIT();
        }

        const uint32_t stg = smb + (kc & 1) * STAGEB;
#pragma unroll
        for (int ks = 0; ks < 2; ks++) {
            const int kb = ks * 16;
            uint32_t ah[4][4], bh[8][2];
#pragma unroll
            for (int mf = 0; mf < 4; mf++) {
                uint32_t addr = stg + (wM + mf * 16 + aRow) * 80 + (kb + aK) * 2;
                ldsm_x4(ah[mf][0], ah[mf][1], ah[mf][2], ah[mf][3], addr);
            }
#pragma unroll
            for (int np = 0; np < 4; np++) {
                uint32_t addr = stg + OFF_B + (wN + np * 16 + bRow) * 80 + (kb + bK) * 2;
                ldsm_x4(bh[2*np][0], bh[2*np][1], bh[2*np+1][0], bh[2*np+1][1], addr);
            }
#pragma unroll
            for (int mf = 0; mf < 4; mf++)
#pragma unroll
                for (int nf = 0; nf < 8; nf++)
                    mma16816(acc[mf][nf], ah[mf], bh[nf]);
        }
    }

#pragma unroll
    for (int nf = 0; nf < 8; nf++) {
        int col = n0 + wN + nf * 8 + t * 2;
        if (col < NOUT) {
            float b0 = bias[col], b1 = bias[col + 1];
#pragma unroll
            for (int mf = 0; mf < 4; mf++) {
                int r0 = m0 + wM + mf * 16 + g;
                float2 v0 = make_float2(acc[mf][nf][0] + b0, acc[mf][nf][1] + b1);
                float2 v1 = make_float2(acc[mf][nf][2] + b0, acc[mf][nf][3] + b1);
                *reinterpret_cast<float2*>(g_H + (size_t)r0 * NOUT + col) = v0;
                *reinterpret_cast<float2*>(g_H + (size_t)(r0 + 8) * NOUT + col) = v1;
            }
        }
    }
}

// ---------------------------------------------------------------------------
// Radix-8 register FFT kernel: 4 frames / 256-thread block, 64 threads/frame.
// ---------------------------------------------------------------------------
struct cf { float x, y; };
__device__ __forceinline__ cf cmul(cf a, cf b){ cf r; r.x=a.x*b.x-a.y*b.y; r.y=a.x*b.y+a.y*b.x; return r; }
__device__ __forceinline__ cf cadd(cf a, cf b){ cf r; r.x=a.x+b.x; r.y=a.y+b.y; return r; }
__device__ __forceinline__ cf csub(cf a, cf b){ cf r; r.x=a.x-b.x; r.y=a.y-b.y; return r; }
__device__ __forceinline__ cf crotp(cf a){ cf r; r.x=-a.y; r.y=a.x; return r; }   // *(+i)

__device__ __forceinline__ void bfly8(cf v[8]) {
    cf b0=v[0], b1=v[4], b2=v[2], b3=v[6], b4=v[1], b5=v[5], b6=v[3], b7=v[7];
    cf t;
    t=b1; b1=csub(b0,t); b0=cadd(b0,t);
    t=b3; b3=csub(b2,t); b2=cadd(b2,t);
    t=b5; b5=csub(b4,t); b4=cadd(b4,t);
    t=b7; b7=csub(b6,t); b6=cadd(b6,t);
    t=b2;        b2=csub(b0,t); b0=cadd(b0,t);
    t=crotp(b3); b3=csub(b1,t); b1=cadd(b1,t);
    t=b6;        b6=csub(b4,t); b4=cadd(b4,t);
    t=crotp(b7); b7=csub(b5,t); b5=cadd(b5,t);
    const float C = 0.70710678118654752440f;
    cf w1; w1.x=C;  w1.y=C;
    cf w3; w3.x=-C; w3.y=C;
    t=b4;          v[4]=csub(b0,t); v[0]=cadd(b0,t);
    t=cmul(b5,w1); v[5]=csub(b1,t); v[1]=cadd(b1,t);
    t=crotp(b6);   v[6]=csub(b2,t); v[2]=cadd(b2,t);
    t=cmul(b7,w3); v[7]=csub(b3,t); v[3]=cadd(b3,t);
}

#define ZP(i) ((i) + ((i) >> 5))   // skewed smem index: 512 -> 528 slots

__global__ __launch_bounds__(256) void fft_kernel()
{
    __shared__ float sr[4][513], si[4][513];
    __shared__ float zr[4][528], zi[4][528];

    const int tid = threadIdx.x;
    const int fl  = tid >> 6;
    const int lt  = tid & 63;
    const int f   = blockIdx.x * 4 + fl;
    const float* __restrict__ h = g_H + (size_t)f * NOUT;

    float* Sr = sr[fl]; float* Si = si[fl];
    float* Zr = zr[fl]; float* Zi = zi[fl];

    for (int k = lt; k < NBINS; k += 64) {
        float mag = fminf(__expf(h[k]), 100.0f);
        float p = h[NBINS + k];
        float s, c;
        __sincosf(p, &s, &c);
        Sr[k] = mag * c;
        Si[k] = mag * s;
    }
    __syncthreads();

    const float ang = 6.283185307179586476e0f / 1024.0f;
    for (int k = lt; k < 512; k += 64) {
        float R, I;
        if (k == 0) {
            R = 0.5f * (Sr[0] + Sr[512]);
            I = 0.5f * (Sr[0] - Sr[512]);
        } else {
            float ar = Sr[k],       ai = Si[k];
            float br = Sr[512 - k], bi = Si[512 - k];
            float Er = 0.5f * (ar + br), Ei = 0.5f * (ai - bi);
            float Dr = 0.5f * (ar - br), Di = 0.5f * (ai + bi);
            float s, c;
            __sincosf(ang * (float)k, &s, &c);
            float Or = Dr * c - Di * s;
            float Oi = Dr * s + Di * c;
            R = Er - Oi;
            I = Ei + Or;
        }
        Zr[ZP(k)] = R;
        Zi[ZP(k)] = I;
    }
    __syncthreads();

    cf v[8];

    {
        int base = (lt & 7) * 8 + (lt >> 3);
#pragma unroll
        for (int m = 0; m < 8; m++) {
            int idx = m * 64 + base;
            v[m].x = Zr[ZP(idx)]; v[m].y = Zi[ZP(idx)];
        }
        bfly8(v);
        __syncthreads();
#pragma unroll
        for (int m = 0; m < 8; m++) {
            int idx = 8 * lt + m;
            Zr[ZP(idx)] = v[m].x; Zi[ZP(idx)] = v[m].y;
        }
    }
    __syncthreads();

    {
        int p  = lt & 7;
        int Gp = (lt >> 3) * 64 + p;
#pragma unroll
        for (int j = 0; j < 8; j++) {
            int idx = Gp + 8 * j;
            v[j].x = Zr[ZP(idx)]; v[j].y = Zi[ZP(idx)];
        }
        float s, c;
        __sincosf(6.283185307179586476e0f * (float)p / 64.0f, &s, &c);
        cf w1; w1.x = c; w1.y = s;
        cf w;  w.x = 1.f; w.y = 0.f;
#pragma unroll
        for (int j = 1; j < 8; j++) {
            w = cmul(w, w1);
            v[j] = cmul(v[j], w);
        }
        bfly8(v);
        __syncthreads();
#pragma unroll
        for (int j = 0; j < 8; j++) {
            int idx = Gp + 8 * j;
            Zr[ZP(idx)] = v[j].x; Zi[ZP(idx)] = v[j].y;
        }
    }
    __syncthreads();

    {
#pragma unroll
        for (int j = 0; j < 8; j++) {
            int idx = lt + 64 * j;
            v[j].x = Zr[ZP(idx)]; v[j].y = Zi[ZP(idx)];
        }
        float s, c;
        __sincosf(6.283185307179586476e0f * (float)lt / 512.0f, &s, &c);
        cf w1; w1.x = c; w1.y = s;
        cf w;  w.x = 1.f; w.y = 0.f;
#pragma unroll
        for (int j = 1; j < 8; j++) {
            w = cmul(w, w1);
            v[j] = cmul(v[j], w);
        }
        bfly8(v);

        float* __restrict__ Fo = g_F + (size_t)f * NFFT;
        const float inv = 1.0f / 512.0f;
#pragma unroll
        for (int j = 0; j < 8; j++) {
            int m = lt + 64 * j;
            float2 wv = *reinterpret_cast<const float2*>(g_win + 2 * m);
            float2 o;
            o.x = v[j].x * inv * wv.x;
            o.y = v[j].y * inv * wv.y;
            *reinterpret_cast<float2*>(Fo + 2 * m) = o;
        }
    }
}

// ---------------------------------------------------------------------------
// Overlap-add: 4 samples/thread, float4 loads (uniform j-range per quad)
// ---------------------------------------------------------------------------
__global__ __launch_bounds__(256) void ola_kernel(float* __restrict__ out)
{
    int q = blockIdx.x * 256 + threadIdx.x;   // quad index
    int o = q * 4;                            // o < OUTB, 4-aligned
    int b = blockIdx.y;
    int t = o + PADQ;                         // t ≡ 0 mod 4 -> quad within one 256-segment

    int jhi = min(t >> 8, SEQ - 1);
    int jlo = (t - 768) >> 8;
    if (jlo < 0) jlo = 0;

    float4 acc = make_float4(0.f, 0.f, 0.f, 0.f);
    float4 env = make_float4(0.f, 0.f, 0.f, 0.f);
    for (int j = jlo; j <= jhi; j++) {
        int n = t - (j << 8);                 // 0..1020, 4-aligned
        float4 fv = *reinterpret_cast<const float4*>(g_F + (((size_t)(b * SEQ + j)) << 10) + n);
        float4 wv = *reinterpret_cast<const float4*>(g_win2 + n);
        acc.x += fv.x; acc.y += fv.y; acc.z += fv.z; acc.w += fv.w;
        env.x += wv.x; env.y += wv.y; env.z += wv.z; env.w += wv.w;
    }
    float4 r;
    r.x = acc.x / env.x; r.y = acc.y / env.y;
    r.z = acc.z / env.z; r.w = acc.w / env.w;
    *reinterpret_cast<float4*>(out + (size_t)b * OUTB + o) = r;
}

// ---------------------------------------------------------------------------
extern "C" void kernel_launch(void* const* d_in, const int* in_sizes, int n_in,
                              void* d_out, int out_size)
{
    (void)in_sizes; (void)n_in; (void)out_size;
    const float* x    = (const float*)d_in[0];
    const float* Wm   = (const float*)d_in[1];
    const float* bias = (const float*)d_in[2];
    float* out = (float*)d_out;

    cudaFuncSetAttribute(gemm_mma_kernel, cudaFuncAttributeMaxDynamicSharedMemorySize, DYNSM);

    window_kernel<<<4, 256>>>();
    convert_x_kernel<<<(MROWS * DIM) / (256 * 4), 256>>>(x);
    {
        dim3 wgrid(NPAD / 32, DIM / 32);   // (36, 16)
        convert_w_kernel<<<wgrid, 256>>>(Wm);
    }

    dim3 ggrid(NPAD / BNg, MROWS / BMg);   // (9, 128)
    gemm_mma_kernel<<<ggrid, 128, DYNSM>>>(bias);

    fft_kernel<<<MROWS / 4, 256>>>();

    dim3 ogrid(OUTB / 1024, BATCH);        // (512, 8)
    ola_kernel<<<ogrid, 256>>>(out);
}

// round 14
// speedup vs baseline: 1.0030x; 1.0030x over previous
#include <cuda_runtime.h>
#include <cuda_fp16.h>
#include <cstdint>

// ---------------------------------------------------------------------------
// Problem shape constants
// ---------------------------------------------------------------------------
#define BATCH   8
#define SEQ     2048
#define DIM     512
#define NOUT    1026          // N_FFT + 2
#define NBINS   513           // N_FFT/2 + 1
#define NFFT    1024
#define HOP     256
#define PADQ    384           // (WIN_LEN - HOP)/2
#define MROWS   (BATCH*SEQ)   // 16384
#define OUTB    524288        // per-batch output length = SEQ*HOP
#define NPAD    1152          // padded N (9 * 128)

// GEMM tiling: CTA 128x128, 4 warps (128 thr), warp tile 64x64
#define BMg     128
#define BNg     128
#define BKg     32
#define NCHUNK  (DIM/BKg)     // 16
#define OFF_B   10240         // A stage: 128 rows x 80B
#define STAGEB  20480         // + B stage: 128 rows x 80B
#define DYNSM   (2*STAGEB)    // 40960

// ---------------------------------------------------------------------------
// Device scratch (allocation-free contract)
// ---------------------------------------------------------------------------
__device__ float          g_H[(size_t)MROWS * NOUT];    // h = xW + b
__device__ float          g_F[(size_t)MROWS * NFFT];    // windowed irfft frames
__device__ unsigned short g_Ax[(size_t)MROWS * DIM];    // fp16 x
__device__ unsigned short g_Wx[(size_t)NPAD * DIM];     // fp16 W^T [n][k]
__device__ float          g_win[NFFT];                  // hann window
__device__ float          g_win2[NFFT];                 // hann^2

// ---------------------------------------------------------------------------
// Portable PTX helpers
// ---------------------------------------------------------------------------
__device__ __forceinline__ uint32_t smem_u32(const void* p) {
    uint32_t a;
    asm("{ .reg .u64 t; cvta.to.shared.u64 t, %1; cvt.u32.u64 %0, t; }"
        : "=r"(a) : "l"(p));
    return a;
}
__device__ __forceinline__ void cp16(uint32_t dst, const void* src) {
    asm volatile("cp.async.cg.shared.global [%0], [%1], 16;"
                 :: "r"(dst), "l"(src) : "memory");
}
#define CP_COMMIT() asm volatile("cp.async.commit_group;" ::: "memory")
#define CP_WAIT0()  asm volatile("cp.async.wait_group 0;" ::: "memory")

__device__ __forceinline__ void mma16816(float* c, const uint32_t* a, const uint32_t* b) {
    asm volatile(
        "mma.sync.aligned.m16n8k16.row.col.f32.f16.f16.f32 "
        "{%0,%1,%2,%3}, {%4,%5,%6,%7}, {%8,%9}, {%0,%1,%2,%3};"
        : "+f"(c[0]), "+f"(c[1]), "+f"(c[2]), "+f"(c[3])
        : "r"(a[0]), "r"(a[1]), "r"(a[2]), "r"(a[3]), "r"(b[0]), "r"(b[1]));
}
__device__ __forceinline__ void ldsm_x4(uint32_t& r0, uint32_t& r1, uint32_t& r2,
                                        uint32_t& r3, uint32_t addr) {
    asm volatile("ldmatrix.sync.aligned.m8n8.x4.shared.b16 {%0,%1,%2,%3}, [%4];"
                 : "=r"(r0), "=r"(r1), "=r"(r2), "=r"(r3) : "r"(addr));
}

// ---------------------------------------------------------------------------
// Prep kernels: fp32 -> fp16
// ---------------------------------------------------------------------------
__global__ __launch_bounds__(256) void convert_x_kernel(const float* __restrict__ x)
{
    size_t v = (size_t)blockIdx.x * 256 + threadIdx.x;   // one float4 per thread
    float4 a = *reinterpret_cast<const float4*>(x + v * 4);
    __half2 p0 = __floats2half2_rn(a.x, a.y);
    __half2 p1 = __floats2half2_rn(a.z, a.w);
    uint2 pv;
    pv.x = *reinterpret_cast<uint32_t*>(&p0);
    pv.y = *reinterpret_cast<uint32_t*>(&p1);
    *reinterpret_cast<uint2*>(g_Ax + v * 4) = pv;
}

// Coalesced W transpose via 32x32 smem tile: read W[k][n], write Wt[n][k] fp16
__global__ __launch_bounds__(256) void convert_w_kernel(const float* __restrict__ W)
{
    __shared__ float tile[32][33];
    const int n0 = blockIdx.x * 32;      // 0..1151 (36 tiles)
    const int k0 = blockIdx.y * 32;      // 0..511  (16 tiles)
    const int tx = threadIdx.x & 31;
    const int ty = threadIdx.x >> 5;     // 0..7

#pragma unroll
    for (int i = 0; i < 32; i += 8) {
        int k = k0 + ty + i;
        int n = n0 + tx;
        tile[ty + i][tx] = (n < NOUT) ? W[(size_t)k * NOUT + n] : 0.0f;
    }
    __syncthreads();
#pragma unroll
    for (int i = 0; i < 32; i += 8) {
        int n = n0 + ty + i;
        int k = k0 + tx;
        __half hv = __float2half_rn(tile[tx][ty + i]);
        g_Wx[(size_t)n * DIM + k] = *reinterpret_cast<unsigned short*>(&hv);
    }
}

__global__ __launch_bounds__(256) void window_kernel()
{
    int n = blockIdx.x * 256 + threadIdx.x;   // 0..1023
    float w = 0.5f * (1.0f - cosf(6.283185307179586476e0f * (float)n / 1024.0f));
    g_win[n]  = w;
    g_win2[n] = w * w;
}

// ---------------------------------------------------------------------------
// fp16 mma.sync GEMM: CTA 128x128, 4 warps, warp tile 64x64,
// 2-stage cp.async, one __syncthreads per chunk.
// ---------------------------------------------------------------------------
__device__ __forceinline__ void load_stage(int s, int kc, int tid,
                                           int m0, int n0, uint32_t smb)
{
    const uint32_t sb = smb + s * STAGEB;
    const int kk = kc * BKg;
#pragma unroll
    for (int i = 0; i < 4; i++) {
        int id = tid + i * 128;            // 0..511
        int row = id >> 2, c = id & 3;     // 128 rows x 4 16B-chunks
        size_t goffA = (size_t)(m0 + row) * DIM + kk + c * 8;
        size_t goffB = (size_t)(n0 + row) * DIM + kk + c * 8;
        cp16(sb + row * 80 + c * 16,         g_Ax + goffA);
        cp16(sb + OFF_B + row * 80 + c * 16, g_Wx + goffB);
    }
}

__global__ __launch_bounds__(128) void gemm_mma_kernel(const float* __restrict__ bias)
{
    extern __shared__ char sm[];
    const int tid  = threadIdx.x;
    const int n0   = blockIdx.x * BNg;
    const int m0   = blockIdx.y * BMg;
    const int wid  = tid >> 5, lane = tid & 31;
    const int g    = lane >> 2, t = lane & 3;
    const int wM   = (wid & 1) * 64;
    const int wN   = (wid >> 1) * 64;
    const uint32_t smb = smem_u32(sm);

    const int mat = lane >> 3;
    const int mr  = lane & 7;
    const int aRow = ((mat & 1) << 3) + mr;
    const int aK   = (mat >> 1) << 3;
    const int bRow = ((mat >> 1) << 3) + mr;
    const int bK   = (mat & 1) << 3;

    float acc[4][8][4];
#pragma unroll
    for (int i = 0; i < 4; i++)
#pragma unroll
        for (int j = 0; j < 8; j++)
#pragma unroll
            for (int q = 0; q < 4; q++) acc[i][j][q] = 0.f;

    load_stage(0, 0, tid, m0, n0, smb);
    CP_COMMIT();

    for (int kc = 0; kc < NCHUNK; kc++) {
        CP_WAIT0();
        __syncthreads();

        if (kc + 1 < NCHUNK) {
            load_stage((kc + 1) & 1, kc + 1, tid, m0, n0, smb);
            CP_COMMIT();
        }

        const uint32_t stg = smb + (kc & 1) * STAGEB;
#pragma unroll
        for (int ks = 0; ks < 2; ks++) {
            const int kb = ks * 16;
            uint32_t ah[4][4], bh[8][2];
#pragma unroll
            for (int mf = 0; mf < 4; mf++) {
                uint32_t addr = stg + (wM + mf * 16 + aRow) * 80 + (kb + aK) * 2;
                ldsm_x4(ah[mf][0], ah[mf][1], ah[mf][2], ah[mf][3], addr);
            }
#pragma unroll
            for (int np = 0; np < 4; np++) {
                uint32_t addr = stg + OFF_B + (wN + np * 16 + bRow) * 80 + (kb + bK) * 2;
                ldsm_x4(bh[2*np][0], bh[2*np][1], bh[2*np+1][0], bh[2*np+1][1], addr);
            }
#pragma unroll
            for (int mf = 0; mf < 4; mf++)
#pragma unroll
                for (int nf = 0; nf < 8; nf++)
                    mma16816(acc[mf][nf], ah[mf], bh[nf]);
        }
    }

#pragma unroll
    for (int nf = 0; nf < 8; nf++) {
        int col = n0 + wN + nf * 8 + t * 2;
        if (col < NOUT) {
            float b0 = bias[col], b1 = bias[col + 1];
#pragma unroll
            for (int mf = 0; mf < 4; mf++) {
                int r0 = m0 + wM + mf * 16 + g;
                float2 v0 = make_float2(acc[mf][nf][0] + b0, acc[mf][nf][1] + b1);
                float2 v1 = make_float2(acc[mf][nf][2] + b0, acc[mf][nf][3] + b1);
                *reinterpret_cast<float2*>(g_H + (size_t)r0 * NOUT + col) = v0;
                *reinterpret_cast<float2*>(g_H + (size_t)(r0 + 8) * NOUT + col) = v1;
            }
        }
    }
}

// ---------------------------------------------------------------------------
// Radix-8 register FFT kernel: 4 frames / 256-thread block, 64 threads/frame.
// ---------------------------------------------------------------------------
struct cf { float x, y; };
__device__ __forceinline__ cf cmul(cf a, cf b){ cf r; r.x=a.x*b.x-a.y*b.y; r.y=a.x*b.y+a.y*b.x; return r; }
__device__ __forceinline__ cf cadd(cf a, cf b){ cf r; r.x=a.x+b.x; r.y=a.y+b.y; return r; }
__device__ __forceinline__ cf csub(cf a, cf b){ cf r; r.x=a.x-b.x; r.y=a.y-b.y; return r; }
__device__ __forceinline__ cf crotp(cf a){ cf r; r.x=-a.y; r.y=a.x; return r; }   // *(+i)

__device__ __forceinline__ void bfly8(cf v[8]) {
    cf b0=v[0], b1=v[4], b2=v[2], b3=v[6], b4=v[1], b5=v[5], b6=v[3], b7=v[7];
    cf t;
    t=b1; b1=csub(b0,t); b0=cadd(b0,t);
    t=b3; b3=csub(b2,t); b2=cadd(b2,t);
    t=b5; b5=csub(b4,t); b4=cadd(b4,t);
    t=b7; b7=csub(b6,t); b6=cadd(b6,t);
    t=b2;        b2=csub(b0,t); b0=cadd(b0,t);
    t=crotp(b3); b3=csub(b1,t); b1=cadd(b1,t);
    t=b6;        b6=csub(b4,t); b4=cadd(b4,t);
    t=crotp(b7); b7=csub(b5,t); b5=cadd(b5,t);
    const float C = 0.70710678118654752440f;
    cf w1; w1.x=C;  w1.y=C;
    cf w3; w3.x=-C; w3.y=C;
    t=b4;          v[4]=csub(b0,t); v[0]=cadd(b0,t);
    t=cmul(b5,w1); v[5]=csub(b1,t); v[1]=cadd(b1,t);
    t=crotp(b6);   v[6]=csub(b2,t); v[2]=cadd(b2,t);
    t=cmul(b7,w3); v[7]=csub(b3,t); v[3]=cadd(b3,t);
}

#define ZP(i) ((i) + ((i) >> 5))   // skewed smem index: 512 -> 528 slots

__global__ __launch_bounds__(256) void fft_kernel()
{
    __shared__ float sr[4][513], si[4][513];
    __shared__ float zr[4][528], zi[4][528];

    const int tid = threadIdx.x;
    const int fl  = tid >> 6;
    const int lt  = tid & 63;
    const int f   = blockIdx.x * 4 + fl;
    const float* __restrict__ h = g_H + (size_t)f * NOUT;

    float* Sr = sr[fl]; float* Si = si[fl];
    float* Zr = zr[fl]; float* Zi = zi[fl];

    for (int k = lt; k < NBINS; k += 64) {
        float mag = fminf(__expf(h[k]), 100.0f);
        float p = h[NBINS + k];
        float s, c;
        __sincosf(p, &s, &c);
        Sr[k] = mag * c;
        Si[k] = mag * s;
    }
    __syncthreads();

    const float ang = 6.283185307179586476e0f / 1024.0f;
    for (int k = lt; k < 512; k += 64) {
        float R, I;
        if (k == 0) {
            R = 0.5f * (Sr[0] + Sr[512]);
            I = 0.5f * (Sr[0] - Sr[512]);
        } else {
            float ar = Sr[k],       ai = Si[k];
            float br = Sr[512 - k], bi = Si[512 - k];
            float Er = 0.5f * (ar + br), Ei = 0.5f * (ai - bi);
            float Dr = 0.5f * (ar - br), Di = 0.5f * (ai + bi);
            float s, c;
            __sincosf(ang * (float)k, &s, &c);
            float Or = Dr * c - Di * s;
            float Oi = Dr * s + Di * c;
            R = Er - Oi;
            I = Ei + Or;
        }
        Zr[ZP(k)] = R;
        Zi[ZP(k)] = I;
    }
    __syncthreads();

    cf v[8];

    {
        int base = (lt & 7) * 8 + (lt >> 3);
#pragma unroll
        for (int m = 0; m < 8; m++) {
            int idx = m * 64 + base;
            v[m].x = Zr[ZP(idx)]; v[m].y = Zi[ZP(idx)];
        }
        bfly8(v);
        __syncthreads();
#pragma unroll
        for (int m = 0; m < 8; m++) {
            int idx = 8 * lt + m;
            Zr[ZP(idx)] = v[m].x; Zi[ZP(idx)] = v[m].y;
        }
    }
    __syncthreads();

    {
        int p  = lt & 7;
        int Gp = (lt >> 3) * 64 + p;
#pragma unroll
        for (int j = 0; j < 8; j++) {
            int idx = Gp + 8 * j;
            v[j].x = Zr[ZP(idx)]; v[j].y = Zi[ZP(idx)];
        }
        float s, c;
        __sincosf(6.283185307179586476e0f * (float)p / 64.0f, &s, &c);
        cf w1; w1.x = c; w1.y = s;
        cf w;  w.x = 1.f; w.y = 0.f;
#pragma unroll
        for (int j = 1; j < 8; j++) {
            w = cmul(w, w1);
            v[j] = cmul(v[j], w);
        }
        bfly8(v);
        __syncthreads();
#pragma unroll
        for (int j = 0; j < 8; j++) {
            int idx = Gp + 8 * j;
            Zr[ZP(idx)] = v[j].x; Zi[ZP(idx)] = v[j].y;
        }
    }
    __syncthreads();

    {
#pragma unroll
        for (int j = 0; j < 8; j++) {
            int idx = lt + 64 * j;
            v[j].x = Zr[ZP(idx)]; v[j].y = Zi[ZP(idx)];
        }
        float s, c;
        __sincosf(6.283185307179586476e0f * (float)lt / 512.0f, &s, &c);
        cf w1; w1.x = c; w1.y = s;
        cf w;  w.x = 1.f; w.y = 0.f;
#pragma unroll
        for (int j = 1; j < 8; j++) {
            w = cmul(w, w1);
            v[j] = cmul(v[j], w);
        }
        bfly8(v);

        float* __restrict__ Fo = g_F + (size_t)f * NFFT;
        const float inv = 1.0f / 512.0f;
#pragma unroll
        for (int j = 0; j < 8; j++) {
            int m = lt + 64 * j;
            float2 wv = *reinterpret_cast<const float2*>(g_win + 2 * m);
            float2 o;
            o.x = v[j].x * inv * wv.x;
            o.y = v[j].y * inv * wv.y;
            *reinterpret_cast<float2*>(Fo + 2 * m) = o;
        }
    }
}

// ---------------------------------------------------------------------------
// Overlap-add: 4 samples/thread, float4 loads (uniform j-range per quad)
// ---------------------------------------------------------------------------
__global__ __launch_bounds__(256) void ola_kernel(float* __restrict__ out)
{
    int q = blockIdx.x * 256 + threadIdx.x;   // quad index
    int o = q * 4;                            // o < OUTB, 4-aligned
    int b = blockIdx.y;
    int t = o + PADQ;                         // t ≡ 0 mod 4 -> quad within one 256-segment

    int jhi = min(t >> 8, SEQ - 1);
    int jlo = (t - 768) >> 8;
    if (jlo < 0) jlo = 0;

    float4 acc = make_float4(0.f, 0.f, 0.f, 0.f);
    float4 env = make_float4(0.f, 0.f, 0.f, 0.f);
    for (int j = jlo; j <= jhi; j++) {
        int n = t - (j << 8);                 // 0..1020, 4-aligned
        float4 fv = *reinterpret_cast<const float4*>(g_F + (((size_t)(b * SEQ + j)) << 10) + n);
        float4 wv = *reinterpret_cast<const float4*>(g_win2 + n);
        acc.x += fv.x; acc.y += fv.y; acc.z += fv.z; acc.w += fv.w;
        env.x += wv.x; env.y += wv.y; env.z += wv.z; env.w += wv.w;
    }
    float4 r;
    r.x = acc.x / env.x; r.y = acc.y / env.y;
    r.z = acc.z / env.z; r.w = acc.w / env.w;
    *reinterpret_cast<float4*>(out + (size_t)b * OUTB + o) = r;
}

// ---------------------------------------------------------------------------
extern "C" void kernel_launch(void* const* d_in, const int* in_sizes, int n_in,
                              void* d_out, int out_size)
{
    (void)in_sizes; (void)n_in; (void)out_size;
    const float* x    = (const float*)d_in[0];
    const float* Wm   = (const float*)d_in[1];
    const float* bias = (const float*)d_in[2];
    float* out = (float*)d_out;

    cudaFuncSetAttribute(gemm_mma_kernel, cudaFuncAttributeMaxDynamicSharedMemorySize, DYNSM);

    window_kernel<<<4, 256>>>();
    convert_x_kernel<<<(MROWS * DIM) / (256 * 4), 256>>>(x);
    {
        dim3 wgrid(NPAD / 32, DIM / 32);   // (36, 16)
        convert_w_kernel<<<wgrid, 256>>>(Wm);
    }

    dim3 ggrid(NPAD / BNg, MROWS / BMg);   // (9, 128)
    gemm_mma_kernel<<<ggrid, 128, DYNSM>>>(bias);

    fft_kernel<<<MROWS / 4, 256>>>();

    dim3 ogrid(OUTB / 1024, BATCH);        // (512, 8)
    ola_kernel<<<ogrid, 256>>>(out);
}